// round 5
// baseline (speedup 1.0000x reference)
#include <cuda_runtime.h>
#include <cstdint>

#define B_DIM 8
#define S_DIM 4096
#define H_DIM 512
#define M_TOT (B_DIM * S_DIM)   // 32768
#define N_TOT (2 * H_DIM)       // 1024
#define K_TOT H_DIM             // 512

// Scratch planes in [b, s, h] layout (same as lstm/out): scan loads are
// warp-coalesced (1 line per warp per load), GEMM epilogue stores are
// fully-efficient float2 stores.
__device__ float g_Q[(size_t)M_TOT * H_DIM];  // 64 MB
__device__ float g_R[(size_t)M_TOT * H_DIM];  // 64 MB

// ---------------------------------------------------------------------------
// Phase 1: C = A * W^T + b, softplus, split into Q/R planes.
// TF32 mma.sync m16n8k8 (row.col). fp32 bits fed directly (HW truncation).
// ---------------------------------------------------------------------------

#define BM 128
#define BN 64
#define BK 32
#define NTHREADS 256
#define SKEW 4

__device__ __forceinline__ float softplus_f(float x) {
    return fmaxf(x, 0.0f) + log1pf(__expf(-fabsf(x)));
}

__device__ __forceinline__ void mma_tf32(float c[4], const uint32_t a[4], const uint32_t b[2]) {
    asm volatile(
        "mma.sync.aligned.m16n8k8.row.col.f32.tf32.tf32.f32 "
        "{%0,%1,%2,%3}, {%4,%5,%6,%7}, {%8,%9}, {%0,%1,%2,%3};"
        : "+f"(c[0]), "+f"(c[1]), "+f"(c[2]), "+f"(c[3])
        : "r"(a[0]), "r"(a[1]), "r"(a[2]), "r"(a[3]), "r"(b[0]), "r"(b[1]));
}

__global__ void __launch_bounds__(NTHREADS)
gemm_softplus_kernel(const float* __restrict__ A,
                     const float* __restrict__ W,
                     const float* __restrict__ bias) {
    __shared__ uint32_t As[BM][BK + SKEW];
    __shared__ uint32_t Bs[BN][BK + SKEW];

    const int bm = blockIdx.y * BM;
    const int bn = blockIdx.x * BN;
    const int tid = threadIdx.x;
    const int warp = tid >> 5;
    const int lane = tid & 31;
    const int wm = (warp >> 1) * 32;
    const int wn = (warp & 1) * 32;

    float acc[2][4][4];
#pragma unroll
    for (int i = 0; i < 2; i++)
#pragma unroll
        for (int j = 0; j < 4; j++)
#pragma unroll
            for (int c = 0; c < 4; c++) acc[i][j][c] = 0.0f;

    float4 a_stage[4];
    float4 b_stage[2];

    const int NKT = K_TOT / BK;  // 16

    {
        const int k0 = 0;
#pragma unroll
        for (int i = 0; i < 4; i++) {
            int idx = tid + i * NTHREADS;
            int row = idx >> 3;
            int c4  = idx & 7;
            a_stage[i] = *(const float4*)(A + (size_t)(bm + row) * K_TOT + k0 + c4 * 4);
        }
#pragma unroll
        for (int i = 0; i < 2; i++) {
            int idx = tid + i * NTHREADS;
            int row = idx >> 3;
            int c4  = idx & 7;
            b_stage[i] = *(const float4*)(W + (size_t)(bn + row) * K_TOT + k0 + c4 * 4);
        }
    }

    for (int kt = 0; kt < NKT; kt++) {
#pragma unroll
        for (int i = 0; i < 4; i++) {
            int idx = tid + i * NTHREADS;
            int row = idx >> 3;
            int c4  = idx & 7;
            uint4 p;
            p.x = __float_as_uint(a_stage[i].x);
            p.y = __float_as_uint(a_stage[i].y);
            p.z = __float_as_uint(a_stage[i].z);
            p.w = __float_as_uint(a_stage[i].w);
            *(uint4*)&As[row][c4 * 4] = p;
        }
#pragma unroll
        for (int i = 0; i < 2; i++) {
            int idx = tid + i * NTHREADS;
            int row = idx >> 3;
            int c4  = idx & 7;
            uint4 p;
            p.x = __float_as_uint(b_stage[i].x);
            p.y = __float_as_uint(b_stage[i].y);
            p.z = __float_as_uint(b_stage[i].z);
            p.w = __float_as_uint(b_stage[i].w);
            *(uint4*)&Bs[row][c4 * 4] = p;
        }
        __syncthreads();

        if (kt + 1 < NKT) {
            const int k0 = (kt + 1) * BK;
#pragma unroll
            for (int i = 0; i < 4; i++) {
                int idx = tid + i * NTHREADS;
                int row = idx >> 3;
                int c4  = idx & 7;
                a_stage[i] = *(const float4*)(A + (size_t)(bm + row) * K_TOT + k0 + c4 * 4);
            }
#pragma unroll
            for (int i = 0; i < 2; i++) {
                int idx = tid + i * NTHREADS;
                int row = idx >> 3;
                int c4  = idx & 7;
                b_stage[i] = *(const float4*)(W + (size_t)(bn + row) * K_TOT + k0 + c4 * 4);
            }
        }

#pragma unroll
        for (int k8 = 0; k8 < 4; k8++) {
            const int c0 = k8 * 8 + (lane & 3);
            uint32_t afrag[2][4];
            uint32_t bfrag[4][2];
#pragma unroll
            for (int tm = 0; tm < 2; tm++) {
                int r0 = wm + tm * 16 + (lane >> 2);
                afrag[tm][0] = As[r0][c0];
                afrag[tm][1] = As[r0 + 8][c0];
                afrag[tm][2] = As[r0][c0 + 4];
                afrag[tm][3] = As[r0 + 8][c0 + 4];
            }
#pragma unroll
            for (int tn = 0; tn < 4; tn++) {
                int rb = wn + tn * 8 + (lane >> 2);
                bfrag[tn][0] = Bs[rb][c0];
                bfrag[tn][1] = Bs[rb][c0 + 4];
            }
#pragma unroll
            for (int tm = 0; tm < 2; tm++)
#pragma unroll
                for (int tn = 0; tn < 4; tn++)
                    mma_tf32(acc[tm][tn], afrag[tm], bfrag[tn]);
        }
        __syncthreads();
    }

    // Epilogue: bias + softplus, [b,s,h] layout, float2 stores.
    const bool is_q = (bn < H_DIM);
    float* plane = is_q ? g_Q : g_R;
    const int col_base_in_plane = is_q ? bn : (bn - H_DIM);

#pragma unroll
    for (int tm = 0; tm < 2; tm++) {
#pragma unroll
        for (int tn = 0; tn < 4; tn++) {
#pragma unroll
            for (int half = 0; half < 2; half++) {
                int row = bm + wm + tm * 16 + (lane >> 2) + half * 8;
                int col = wn + tn * 8 + (lane & 3) * 2;
                int gcol = bn + col;
                float v0 = acc[tm][tn][half * 2 + 0] + __ldg(&bias[gcol]);
                float v1 = acc[tm][tn][half * 2 + 1] + __ldg(&bias[gcol + 1]);
                float2 sp;
                sp.x = softplus_f(v0);
                sp.y = softplus_f(v1);
                *(float2*)&plane[(size_t)row * H_DIM + col_base_in_plane + col] = sp;
            }
        }
    }
}

// ---------------------------------------------------------------------------
// Phase 2: Kalman scan, register-pipelined with 4 rotating buffers
// (prefetch distance 3 chunks ≈ 720 cyc > DRAM latency). All of z/q/r/out
// are [b,s,h]: every warp load/store touches exactly one 128B line.
// ---------------------------------------------------------------------------
#define U 8
#define NCH (S_DIM / U)   // 512
#define NBUF 4

struct Chunk {
    float z[U];
    float q[U];
    float r[U];
};

__device__ __forceinline__ void load_chunk(Chunk& ch,
                                           const float* __restrict__ zp,
                                           const float* __restrict__ qp,
                                           const float* __restrict__ rp,
                                           int c) {
    const size_t base = (size_t)c * U * H_DIM;
#pragma unroll
    for (int i = 0; i < U; i++) {
        size_t off = base + (size_t)i * H_DIM;
        ch.z[i] = __ldg(zp + off);
        ch.q[i] = __ldg(qp + off);
        ch.r[i] = __ldg(rp + off);
    }
}

__device__ __forceinline__ void compute_chunk(const Chunk& ch,
                                              float& state, float& P,
                                              float* __restrict__ op, int c) {
    float* oc = op + (size_t)c * U * H_DIM;
#pragma unroll
    for (int i = 0; i < U; i++) {
        float P_pred = P + ch.q[i];
        float rr = ch.r[i] + 1e-6f;
        float denom = P_pred + rr;
        float inv;
        asm("rcp.approx.f32 %0, %1;" : "=f"(inv) : "f"(denom));
        float K = P_pred * inv;
        state = fmaf(K, ch.z[i] - state, state);
        P = P_pred * rr * inv;   // == (1-K)*P_pred
        oc[(size_t)i * H_DIM] = state;
    }
}

__global__ void __launch_bounds__(32, 1)
scan_kernel(const float* __restrict__ lstm, float* __restrict__ out) {
    int idx = blockIdx.x * 32 + threadIdx.x;  // 0..4095 == chain id
    int b = idx >> 9;
    int h = idx & 511;

    const size_t chain_off = (size_t)b * S_DIM * H_DIM + h;
    const float* zp = lstm + chain_off;
    const float* qp = g_Q + chain_off;
    const float* rp = g_R + chain_off;
    float* op = out + chain_off;

    float state = zp[0];
    float P = 0.1f;

    Chunk buf0, buf1, buf2, buf3;

    load_chunk(buf0, zp, qp, rp, 0);
    load_chunk(buf1, zp, qp, rp, 1);
    load_chunk(buf2, zp, qp, rp, 2);

    for (int c = 0; c < NCH; c += NBUF) {
        load_chunk(buf3, zp, qp, rp, c + 3);              // c+3 <= 511 always
        compute_chunk(buf0, state, P, op, c);
        if (c + 4 < NCH) load_chunk(buf0, zp, qp, rp, c + 4);
        compute_chunk(buf1, state, P, op, c + 1);
        if (c + 5 < NCH) load_chunk(buf1, zp, qp, rp, c + 5);
        compute_chunk(buf2, state, P, op, c + 2);
        if (c + 6 < NCH) load_chunk(buf2, zp, qp, rp, c + 6);
        compute_chunk(buf3, state, P, op, c + 3);
    }
}

extern "C" void kernel_launch(void* const* d_in, const int* in_sizes, int n_in,
                              void* d_out, int out_size) {
    const float* lstm = (const float*)d_in[0];
    const float* W    = (const float*)d_in[1];
    const float* bias = (const float*)d_in[2];
    float* out = (float*)d_out;

    dim3 grid(N_TOT / BN, M_TOT / BM);  // (16, 256)
    gemm_softplus_kernel<<<grid, NTHREADS>>>(lstm, W, bias);

    scan_kernel<<<128, 32>>>(lstm, out);
}

// round 6
// speedup vs baseline: 1.2847x; 1.2847x over previous
#include <cuda_runtime.h>
#include <cstdint>

#define B_DIM 8
#define S_DIM 4096
#define H_DIM 512
#define M_TOT (B_DIM * S_DIM)   // 32768
#define N_TOT (2 * H_DIM)       // 1024
#define K_TOT H_DIM             // 512

// Scratch planes in [b, s, h] layout (same as lstm/out).
__device__ float g_Q[(size_t)M_TOT * H_DIM];  // 64 MB
__device__ float g_R[(size_t)M_TOT * H_DIM];  // 64 MB

// ---------------------------------------------------------------------------
// Phase 1: C = A * W^T + b, softplus, split into Q/R planes.
// TF32 mma.sync m16n8k8 (row.col). fp32 bits fed directly (HW truncation).
// ---------------------------------------------------------------------------

#define BM 128
#define BN 64
#define BK 32
#define NTHREADS 256
#define SKEW 4

__device__ __forceinline__ float softplus_f(float x) {
    return fmaxf(x, 0.0f) + log1pf(__expf(-fabsf(x)));
}

__device__ __forceinline__ void mma_tf32(float c[4], const uint32_t a[4], const uint32_t b[2]) {
    asm volatile(
        "mma.sync.aligned.m16n8k8.row.col.f32.tf32.tf32.f32 "
        "{%0,%1,%2,%3}, {%4,%5,%6,%7}, {%8,%9}, {%0,%1,%2,%3};"
        : "+f"(c[0]), "+f"(c[1]), "+f"(c[2]), "+f"(c[3])
        : "r"(a[0]), "r"(a[1]), "r"(a[2]), "r"(a[3]), "r"(b[0]), "r"(b[1]));
}

__global__ void __launch_bounds__(NTHREADS)
gemm_softplus_kernel(const float* __restrict__ A,
                     const float* __restrict__ W,
                     const float* __restrict__ bias) {
    __shared__ uint32_t As[BM][BK + SKEW];
    __shared__ uint32_t Bs[BN][BK + SKEW];

    const int bm = blockIdx.y * BM;
    const int bn = blockIdx.x * BN;
    const int tid = threadIdx.x;
    const int warp = tid >> 5;
    const int lane = tid & 31;
    const int wm = (warp >> 1) * 32;
    const int wn = (warp & 1) * 32;

    float acc[2][4][4];
#pragma unroll
    for (int i = 0; i < 2; i++)
#pragma unroll
        for (int j = 0; j < 4; j++)
#pragma unroll
            for (int c = 0; c < 4; c++) acc[i][j][c] = 0.0f;

    float4 a_stage[4];
    float4 b_stage[2];

    const int NKT = K_TOT / BK;  // 16

    {
        const int k0 = 0;
#pragma unroll
        for (int i = 0; i < 4; i++) {
            int idx = tid + i * NTHREADS;
            int row = idx >> 3;
            int c4  = idx & 7;
            a_stage[i] = *(const float4*)(A + (size_t)(bm + row) * K_TOT + k0 + c4 * 4);
        }
#pragma unroll
        for (int i = 0; i < 2; i++) {
            int idx = tid + i * NTHREADS;
            int row = idx >> 3;
            int c4  = idx & 7;
            b_stage[i] = *(const float4*)(W + (size_t)(bn + row) * K_TOT + k0 + c4 * 4);
        }
    }

    for (int kt = 0; kt < NKT; kt++) {
#pragma unroll
        for (int i = 0; i < 4; i++) {
            int idx = tid + i * NTHREADS;
            int row = idx >> 3;
            int c4  = idx & 7;
            uint4 p;
            p.x = __float_as_uint(a_stage[i].x);
            p.y = __float_as_uint(a_stage[i].y);
            p.z = __float_as_uint(a_stage[i].z);
            p.w = __float_as_uint(a_stage[i].w);
            *(uint4*)&As[row][c4 * 4] = p;
        }
#pragma unroll
        for (int i = 0; i < 2; i++) {
            int idx = tid + i * NTHREADS;
            int row = idx >> 3;
            int c4  = idx & 7;
            uint4 p;
            p.x = __float_as_uint(b_stage[i].x);
            p.y = __float_as_uint(b_stage[i].y);
            p.z = __float_as_uint(b_stage[i].z);
            p.w = __float_as_uint(b_stage[i].w);
            *(uint4*)&Bs[row][c4 * 4] = p;
        }
        __syncthreads();

        if (kt + 1 < NKT) {
            const int k0 = (kt + 1) * BK;
#pragma unroll
            for (int i = 0; i < 4; i++) {
                int idx = tid + i * NTHREADS;
                int row = idx >> 3;
                int c4  = idx & 7;
                a_stage[i] = *(const float4*)(A + (size_t)(bm + row) * K_TOT + k0 + c4 * 4);
            }
#pragma unroll
            for (int i = 0; i < 2; i++) {
                int idx = tid + i * NTHREADS;
                int row = idx >> 3;
                int c4  = idx & 7;
                b_stage[i] = *(const float4*)(W + (size_t)(bn + row) * K_TOT + k0 + c4 * 4);
            }
        }

#pragma unroll
        for (int k8 = 0; k8 < 4; k8++) {
            const int c0 = k8 * 8 + (lane & 3);
            uint32_t afrag[2][4];
            uint32_t bfrag[4][2];
#pragma unroll
            for (int tm = 0; tm < 2; tm++) {
                int r0 = wm + tm * 16 + (lane >> 2);
                afrag[tm][0] = As[r0][c0];
                afrag[tm][1] = As[r0 + 8][c0];
                afrag[tm][2] = As[r0][c0 + 4];
                afrag[tm][3] = As[r0 + 8][c0 + 4];
            }
#pragma unroll
            for (int tn = 0; tn < 4; tn++) {
                int rb = wn + tn * 8 + (lane >> 2);
                bfrag[tn][0] = Bs[rb][c0];
                bfrag[tn][1] = Bs[rb][c0 + 4];
            }
#pragma unroll
            for (int tm = 0; tm < 2; tm++)
#pragma unroll
                for (int tn = 0; tn < 4; tn++)
                    mma_tf32(acc[tm][tn], afrag[tm], bfrag[tn]);
        }
        __syncthreads();
    }

    const bool is_q = (bn < H_DIM);
    float* plane = is_q ? g_Q : g_R;
    const int col_base_in_plane = is_q ? bn : (bn - H_DIM);

#pragma unroll
    for (int tm = 0; tm < 2; tm++) {
#pragma unroll
        for (int tn = 0; tn < 4; tn++) {
#pragma unroll
            for (int half = 0; half < 2; half++) {
                int row = bm + wm + tm * 16 + (lane >> 2) + half * 8;
                int col = wn + tn * 8 + (lane & 3) * 2;
                int gcol = bn + col;
                float v0 = acc[tm][tn][half * 2 + 0] + __ldg(&bias[gcol]);
                float v1 = acc[tm][tn][half * 2 + 1] + __ldg(&bias[gcol + 1]);
                float2 sp;
                sp.x = softplus_f(v0);
                sp.y = softplus_f(v1);
                *(float2*)&plane[(size_t)row * H_DIM + col_base_in_plane + col] = sp;
            }
        }
    }
}

// ---------------------------------------------------------------------------
// Phase 2: Kalman scan, cp.async (LDGSTS) SMEM ring pipeline.
// LDGSTS is not bounded by the per-warp LDG scoreboard cap (M_max~55) that
// serialized the register-pipelined versions. 8-slot ring (~7 chunks of
// latency cover ~ 1600+ cyc >> DRAM latency). 6 cp.async (16B) per chunk.
// ---------------------------------------------------------------------------
#define U 8
#define NCH (S_DIM / U)   // 512
#define DEPTH 8           // ring slots (power of 2)

__global__ void __launch_bounds__(32, 1)
scan_kernel(const float* __restrict__ lstm, float* __restrict__ out) {
    // sbuf[slot][array(z,q,r)][row][lane]
    __shared__ float sbuf[DEPTH][3][U][32];

    const int lane = threadIdx.x;
    const int idx = blockIdx.x * 32 + lane;   // chain id 0..4095
    const int b = idx >> 9;
    const int h0 = (blockIdx.x * 32) & 511;   // block-uniform h base

    const size_t block_off = (size_t)b * S_DIM * H_DIM + h0;
    const float* zb = lstm + block_off;
    const float* qb = g_Q + block_off;
    const float* rb = g_R + block_off;
    float* op = out + (size_t)b * S_DIM * H_DIM + h0 + lane;

    // cp.async source lane mapping: 16B per lane, 4 rows per instruction.
    const int cp_row = lane >> 3;        // 0..3
    const int cp_col = (lane & 7) * 4;   // float offset within row

    const float* srcs[3] = { zb, qb, rb };

    // issue one chunk into ring slot (c & (DEPTH-1)); one commit group.
    auto issue = [&](int c) {
        int slot = c & (DEPTH - 1);
#pragma unroll
        for (int a = 0; a < 3; a++) {
#pragma unroll
            for (int g = 0; g < 2; g++) {
                int row = g * 4 + cp_row;
                const float* src = srcs[a] + ((size_t)c * U + row) * H_DIM + cp_col;
                uint32_t dst = (uint32_t)__cvta_generic_to_shared(&sbuf[slot][a][row][cp_col]);
                asm volatile("cp.async.cg.shared.global [%0], [%1], 16;"
                             :: "r"(dst), "l"(src) : "memory");
            }
        }
        asm volatile("cp.async.commit_group;" ::: "memory");
    };

    float state = __ldg(zb + lane);   // lstm[b,0,h]
    float P = 0.1f;

#pragma unroll
    for (int d = 0; d < DEPTH - 1; d++) issue(d);

    for (int c = 0; c < NCH; c++) {
        asm volatile("cp.async.wait_group %0;" :: "n"(DEPTH - 2) : "memory");

        const int slot = c & (DEPTH - 1);
        float* oc = op + (size_t)c * U * H_DIM;
#pragma unroll
        for (int i = 0; i < U; i++) {
            float z = sbuf[slot][0][i][lane];
            float q = sbuf[slot][1][i][lane];
            float r = sbuf[slot][2][i][lane];
            float P_pred = P + q;
            float rr = r + 1e-6f;
            float denom = P_pred + rr;
            float inv;
            asm("rcp.approx.f32 %0, %1;" : "=f"(inv) : "f"(denom));
            float K = P_pred * inv;
            state = fmaf(K, z - state, state);
            P = P_pred * rr * inv;   // == (1-K)*P_pred
            oc[(size_t)i * H_DIM] = state;
        }

        if (c + DEPTH - 1 < NCH) issue(c + DEPTH - 1);
    }
}

extern "C" void kernel_launch(void* const* d_in, const int* in_sizes, int n_in,
                              void* d_out, int out_size) {
    const float* lstm = (const float*)d_in[0];
    const float* W    = (const float*)d_in[1];
    const float* bias = (const float*)d_in[2];
    float* out = (float*)d_out;

    dim3 grid(N_TOT / BN, M_TOT / BM);  // (16, 256)
    gemm_softplus_kernel<<<grid, NTHREADS>>>(lstm, W, bias);

    scan_kernel<<<128, 32>>>(lstm, out);
}

// round 8
// speedup vs baseline: 1.4613x; 1.1375x over previous
#include <cuda_runtime.h>
#include <cstdint>

#define B_DIM 8
#define S_DIM 4096
#define H_DIM 512
#define M_TOT (B_DIM * S_DIM)   // 32768
#define N_TOT (2 * H_DIM)       // 1024
#define K_TOT H_DIM             // 512

// Scratch planes in [b, s, h] layout (same as lstm/out).
__device__ float g_Q[(size_t)M_TOT * H_DIM];  // 64 MB
__device__ float g_R[(size_t)M_TOT * H_DIM];  // 64 MB

// ===========================================================================
// Phase 1: C = A*W^T + b, softplus -> Q/R planes.
// mma.sync m16n8k8 tf32 (fp32 bits fed directly; HW truncation, ~2e-4).
// BM=128, BN=256, BK=32; 8 warps x (64x64) warp tiles; 3-stage cp.async ring.
// ===========================================================================

#define BM2 128
#define BN2 256
#define BK2 32
#define NKT2 (K_TOT / BK2)      // 16
#define ROWW 36                 // BK2 + 4 skew (floats); 36 mod 32 = 4 -> conflict-free
#define A_FLOATS (BM2 * ROWW)   // 4608
#define B_FLOATS (BN2 * ROWW)   // 9216
#define STAGE_FLOATS (A_FLOATS + B_FLOATS)   // 13824
#define NSTAGE 3
#define DYN_BYTES (NSTAGE * STAGE_FLOATS * 4)  // 165888

__device__ __forceinline__ float softplus_f(float x) {
    return fmaxf(x, 0.0f) + log1pf(__expf(-fabsf(x)));
}

__device__ __forceinline__ void mma_tf32(float c[4], const uint32_t a[4], const uint32_t b[2]) {
    asm volatile(
        "mma.sync.aligned.m16n8k8.row.col.f32.tf32.tf32.f32 "
        "{%0,%1,%2,%3}, {%4,%5,%6,%7}, {%8,%9}, {%0,%1,%2,%3};"
        : "+f"(c[0]), "+f"(c[1]), "+f"(c[2]), "+f"(c[3])
        : "r"(a[0]), "r"(a[1]), "r"(a[2]), "r"(a[3]), "r"(b[0]), "r"(b[1]));
}

__global__ void __launch_bounds__(256, 1)
gemm_softplus_kernel(const float* __restrict__ A,
                     const float* __restrict__ W,
                     const float* __restrict__ bias) {
    extern __shared__ float dynf[];

    const int tid  = threadIdx.x;
    const int warp = tid >> 5;
    const int lane = tid & 31;
    const int bm = blockIdx.y * BM2;
    const int bn = blockIdx.x * BN2;

    // warp grid 2 rows x 4 cols; warp tile 64x64
    const int wm = (warp >> 2) * 64;
    const int wn = (warp & 3) * 64;

    float acc[4][8][4];
#pragma unroll
    for (int i = 0; i < 4; i++)
#pragma unroll
        for (int j = 0; j < 8; j++)
#pragma unroll
            for (int c = 0; c < 4; c++) acc[i][j][c] = 0.0f;

    // ---- cp.async stage loader ------------------------------------------
    auto issue_stage = [&](int kt) {
        const int s = kt % NSTAGE;
        float* As = dynf + s * STAGE_FLOATS;
        float* Bs = As + A_FLOATS;
        const int kcol = kt * BK2;
#pragma unroll
        for (int i = 0; i < 4; i++) {               // A: 128 rows x 8 chunks
            int j = tid + i * 256;
            int row = j >> 3, cb = j & 7;
            const float* src = A + (size_t)(bm + row) * K_TOT + kcol + cb * 4;
            uint32_t dst = (uint32_t)__cvta_generic_to_shared(As + row * ROWW + cb * 4);
            asm volatile("cp.async.cg.shared.global [%0], [%1], 16;"
                         :: "r"(dst), "l"(src) : "memory");
        }
#pragma unroll
        for (int i = 0; i < 8; i++) {               // B: 256 rows x 8 chunks
            int j = tid + i * 256;
            int row = j >> 3, cb = j & 7;
            const float* src = W + (size_t)(bn + row) * K_TOT + kcol + cb * 4;
            uint32_t dst = (uint32_t)__cvta_generic_to_shared(Bs + row * ROWW + cb * 4);
            asm volatile("cp.async.cg.shared.global [%0], [%1], 16;"
                         :: "r"(dst), "l"(src) : "memory");
        }
        asm volatile("cp.async.commit_group;" ::: "memory");
    };

    issue_stage(0);
    issue_stage(1);

    for (int kt = 0; kt < NKT2; kt++) {
        if (kt == NKT2 - 1) asm volatile("cp.async.wait_group 0;" ::: "memory");
        else                asm volatile("cp.async.wait_group 1;" ::: "memory");
        __syncthreads();

        const int s = kt % NSTAGE;
        const uint32_t* As = (const uint32_t*)(dynf + s * STAGE_FLOATS);
        const uint32_t* Bs = As + A_FLOATS;

#pragma unroll
        for (int k8 = 0; k8 < 4; k8++) {
            const int c0 = k8 * 8 + (lane & 3);
            uint32_t afrag[4][4];
            uint32_t bfrag[8][2];
#pragma unroll
            for (int tm = 0; tm < 4; tm++) {
                int r0 = wm + tm * 16 + (lane >> 2);
                // verified m16n8k8 tf32 A fragment order:
                // a0=(g,c0) a1=(g+8,c0) a2=(g,c0+4) a3=(g+8,c0+4)
                afrag[tm][0] = As[r0 * ROWW + c0];
                afrag[tm][1] = As[(r0 + 8) * ROWW + c0];
                afrag[tm][2] = As[r0 * ROWW + c0 + 4];
                afrag[tm][3] = As[(r0 + 8) * ROWW + c0 + 4];
            }
#pragma unroll
            for (int tn = 0; tn < 8; tn++) {
                int rb = wn + tn * 8 + (lane >> 2);
                bfrag[tn][0] = Bs[rb * ROWW + c0];
                bfrag[tn][1] = Bs[rb * ROWW + c0 + 4];
            }
#pragma unroll
            for (int tm = 0; tm < 4; tm++)
#pragma unroll
                for (int tn = 0; tn < 8; tn++)
                    mma_tf32(acc[tm][tn], afrag[tm], bfrag[tn]);
        }
        __syncthreads();

        if (kt + 2 < NKT2) issue_stage(kt + 2);
    }

    // ---- Epilogue: bias + softplus, float2 stores into Q or R plane -------
    const bool is_q = (bn < H_DIM);
    float* plane = is_q ? g_Q : g_R;
    const int col_plane0 = bn & (H_DIM - 1);

#pragma unroll
    for (int tm = 0; tm < 4; tm++) {
#pragma unroll
        for (int tn = 0; tn < 8; tn++) {
#pragma unroll
            for (int half = 0; half < 2; half++) {
                int row = bm + wm + tm * 16 + (lane >> 2) + half * 8;
                int col = wn + tn * 8 + (lane & 3) * 2;
                int gcol = bn + col;
                float v0 = acc[tm][tn][half * 2 + 0] + __ldg(&bias[gcol]);
                float v1 = acc[tm][tn][half * 2 + 1] + __ldg(&bias[gcol + 1]);
                float2 sp;
                sp.x = softplus_f(v0);
                sp.y = softplus_f(v1);
                *(float2*)&plane[(size_t)row * H_DIM + col_plane0 + col] = sp;
            }
        }
    }
}

// ---------------------------------------------------------------------------
// Phase 2: Kalman scan, cp.async SMEM ring pipeline (unchanged from R6).
// ---------------------------------------------------------------------------
#define U 8
#define NCH (S_DIM / U)   // 512
#define DEPTH 8           // ring slots (power of 2)

__global__ void __launch_bounds__(32, 1)
scan_kernel(const float* __restrict__ lstm, float* __restrict__ out) {
    __shared__ float sbuf[DEPTH][3][U][32];

    const int lane = threadIdx.x;
    const int idx = blockIdx.x * 32 + lane;   // chain id 0..4095
    const int b = idx >> 9;
    const int h0 = (blockIdx.x * 32) & 511;   // block-uniform h base

    const size_t block_off = (size_t)b * S_DIM * H_DIM + h0;
    const float* zb = lstm + block_off;
    const float* qb = g_Q + block_off;
    const float* rb = g_R + block_off;
    float* op = out + (size_t)b * S_DIM * H_DIM + h0 + lane;

    const int cp_row = lane >> 3;        // 0..3
    const int cp_col = (lane & 7) * 4;   // float offset within row

    const float* srcs[3] = { zb, qb, rb };

    auto issue = [&](int c) {
        int slot = c & (DEPTH - 1);
#pragma unroll
        for (int a = 0; a < 3; a++) {
#pragma unroll
            for (int g = 0; g < 2; g++) {
                int row = g * 4 + cp_row;
                const float* src = srcs[a] + ((size_t)c * U + row) * H_DIM + cp_col;
                uint32_t dst = (uint32_t)__cvta_generic_to_shared(&sbuf[slot][a][row][cp_col]);
                asm volatile("cp.async.cg.shared.global [%0], [%1], 16;"
                             :: "r"(dst), "l"(src) : "memory");
            }
        }
        asm volatile("cp.async.commit_group;" ::: "memory");
    };

    float state = __ldg(zb + lane);   // lstm[b,0,h]
    float P = 0.1f;

#pragma unroll
    for (int d = 0; d < DEPTH - 1; d++) issue(d);

    for (int c = 0; c < NCH; c++) {
        asm volatile("cp.async.wait_group %0;" :: "n"(DEPTH - 2) : "memory");

        const int slot = c & (DEPTH - 1);
        float* oc = op + (size_t)c * U * H_DIM;
#pragma unroll
        for (int i = 0; i < U; i++) {
            float z = sbuf[slot][0][i][lane];
            float q = sbuf[slot][1][i][lane];
            float r = sbuf[slot][2][i][lane];
            float P_pred = P + q;
            float rr = r + 1e-6f;
            float denom = P_pred + rr;
            float inv;
            asm("rcp.approx.f32 %0, %1;" : "=f"(inv) : "f"(denom));
            float K = P_pred * inv;
            state = fmaf(K, z - state, state);
            P = P_pred * rr * inv;   // == (1-K)*P_pred
            oc[(size_t)i * H_DIM] = state;
        }

        if (c + DEPTH - 1 < NCH) issue(c + DEPTH - 1);
    }
}

extern "C" void kernel_launch(void* const* d_in, const int* in_sizes, int n_in,
                              void* d_out, int out_size) {
    const float* lstm = (const float*)d_in[0];
    const float* W    = (const float*)d_in[1];
    const float* bias = (const float*)d_in[2];
    float* out = (float*)d_out;

    cudaFuncSetAttribute(gemm_softplus_kernel,
                         cudaFuncAttributeMaxDynamicSharedMemorySize, DYN_BYTES);

    dim3 grid2(N_TOT / BN2, M_TOT / BM2);   // (4, 256)
    gemm_softplus_kernel<<<grid2, 256, DYN_BYTES>>>(lstm, W, bias);

    scan_kernel<<<128, 32>>>(lstm, out);
}

// round 9
// speedup vs baseline: 1.8218x; 1.2467x over previous
#include <cuda_runtime.h>
#include <cuda_fp16.h>
#include <cstdint>

#define B_DIM 8
#define S_DIM 4096
#define H_DIM 512
#define M_TOT (B_DIM * S_DIM)   // 32768
#define N_TOT (2 * H_DIM)       // 1024
#define K_TOT H_DIM             // 512

// Scratch planes in [b, s, h] layout (same as lstm/out).
__device__ float g_Q[(size_t)M_TOT * H_DIM];  // 64 MB
__device__ float g_R[(size_t)M_TOT * H_DIM];  // 64 MB
// fp16 copies of A and W for the 2x-rate fp16 tensor path.
__device__ __half g_Ah[(size_t)M_TOT * K_TOT];  // 32 MB
__device__ __half g_Wh[(size_t)N_TOT * K_TOT];  // 1 MB

// ===========================================================================
// Pre-pass: fp32 -> fp16 conversion (grid-stride, float4 -> half2 x2).
// ===========================================================================
__global__ void cvt_fp16_kernel(const float* __restrict__ src,
                                __half* __restrict__ dst, int n4) {
    int i = blockIdx.x * blockDim.x + threadIdx.x;
    int stride = gridDim.x * blockDim.x;
    for (; i < n4; i += stride) {
        float4 v = ((const float4*)src)[i];
        __half2 h0 = __floats2half2_rn(v.x, v.y);
        __half2 h1 = __floats2half2_rn(v.z, v.w);
        ((__half2*)dst)[2 * i]     = h0;
        ((__half2*)dst)[2 * i + 1] = h1;
    }
}

// ===========================================================================
// Phase 1: C = A*W^T + b, softplus -> Q/R planes.
// fp16 mma.sync m16n8k16 (same 10-bit mantissa as tf32, 2x rate).
// BM=128, BN=256, BK=64 halves; 8 warps x (64x64) tiles; 3-stage cp.async.
// ===========================================================================

#define BM2 128
#define BN2 256
#define BKH 64                    // k per ktile (halves) = 128B rows
#define NKTH (K_TOT / BKH)        // 8
#define ROWH 72                   // halves per row incl. 8-half skew (144B)
#define A_HALVES (BM2 * ROWH)     // 9216
#define B_HALVES (BN2 * ROWH)     // 18432
#define STAGE_HALVES (A_HALVES + B_HALVES)     // 27648
#define NSTAGE 3
#define DYN_BYTES (NSTAGE * STAGE_HALVES * 2)  // 165888

__device__ __forceinline__ float softplus_f(float x) {
    return fmaxf(x, 0.0f) + log1pf(__expf(-fabsf(x)));
}

__device__ __forceinline__ void mma_f16(float c[4], const uint32_t a[4], const uint32_t b[2]) {
    asm volatile(
        "mma.sync.aligned.m16n8k16.row.col.f32.f16.f16.f32 "
        "{%0,%1,%2,%3}, {%4,%5,%6,%7}, {%8,%9}, {%0,%1,%2,%3};"
        : "+f"(c[0]), "+f"(c[1]), "+f"(c[2]), "+f"(c[3])
        : "r"(a[0]), "r"(a[1]), "r"(a[2]), "r"(a[3]), "r"(b[0]), "r"(b[1]));
}

__global__ void __launch_bounds__(256, 1)
gemm_softplus_kernel(const __half* __restrict__ A,
                     const __half* __restrict__ W,
                     const float* __restrict__ bias) {
    extern __shared__ __half dynh[];

    const int tid  = threadIdx.x;
    const int warp = tid >> 5;
    const int lane = tid & 31;
    const int bm = blockIdx.y * BM2;
    const int bn = blockIdx.x * BN2;

    // warp grid 2 rows x 4 cols; warp tile 64x64
    const int wm = (warp >> 2) * 64;
    const int wn = (warp & 3) * 64;

    float acc[4][8][4];
#pragma unroll
    for (int i = 0; i < 4; i++)
#pragma unroll
        for (int j = 0; j < 8; j++)
#pragma unroll
            for (int c = 0; c < 4; c++) acc[i][j][c] = 0.0f;

    // ---- cp.async stage loader (16B = 8 halves per chunk) -----------------
    auto issue_stage = [&](int kt) {
        const int s = kt % NSTAGE;
        __half* As = dynh + s * STAGE_HALVES;
        __half* Bs = As + A_HALVES;
        const int kcol = kt * BKH;
#pragma unroll
        for (int i = 0; i < 4; i++) {               // A: 128 rows x 8 chunks
            int j = tid + i * 256;
            int row = j >> 3, cb = j & 7;
            const __half* src = A + (size_t)(bm + row) * K_TOT + kcol + cb * 8;
            uint32_t dst = (uint32_t)__cvta_generic_to_shared(As + row * ROWH + cb * 8);
            asm volatile("cp.async.cg.shared.global [%0], [%1], 16;"
                         :: "r"(dst), "l"(src) : "memory");
        }
#pragma unroll
        for (int i = 0; i < 8; i++) {               // B: 256 rows x 8 chunks
            int j = tid + i * 256;
            int row = j >> 3, cb = j & 7;
            const __half* src = W + (size_t)(bn + row) * K_TOT + kcol + cb * 8;
            uint32_t dst = (uint32_t)__cvta_generic_to_shared(Bs + row * ROWH + cb * 8);
            asm volatile("cp.async.cg.shared.global [%0], [%1], 16;"
                         :: "r"(dst), "l"(src) : "memory");
        }
        asm volatile("cp.async.commit_group;" ::: "memory");
    };

    issue_stage(0);
    issue_stage(1);

    for (int kt = 0; kt < NKTH; kt++) {
        if (kt == NKTH - 1) asm volatile("cp.async.wait_group 0;" ::: "memory");
        else                asm volatile("cp.async.wait_group 1;" ::: "memory");
        __syncthreads();

        const int s = kt % NSTAGE;
        const uint32_t* As32 = (const uint32_t*)(dynh + s * STAGE_HALVES);
        const uint32_t* Bs32 = As32 + A_HALVES / 2;

#pragma unroll
        for (int ks = 0; ks < 4; ks++) {            // 4 x k16 per ktile
            // index units: half2 words; row stride = ROWH/2 = 36 words
            const int c0h = ks * 8 + (lane & 3);    // k/2 within row
            uint32_t afrag[4][4];
            uint32_t bfrag[8][2];
#pragma unroll
            for (int tm = 0; tm < 4; tm++) {
                int r0 = wm + tm * 16 + (lane >> 2);
                // m16n8k16 f16 A: a0=(g,k) a1=(g+8,k) a2=(g,k+8) a3=(g+8,k+8)
                afrag[tm][0] = As32[r0 * 36 + c0h];
                afrag[tm][1] = As32[(r0 + 8) * 36 + c0h];
                afrag[tm][2] = As32[r0 * 36 + c0h + 4];
                afrag[tm][3] = As32[(r0 + 8) * 36 + c0h + 4];
            }
#pragma unroll
            for (int tn = 0; tn < 8; tn++) {
                int rb = wn + tn * 8 + (lane >> 2);
                bfrag[tn][0] = Bs32[rb * 36 + c0h];
                bfrag[tn][1] = Bs32[rb * 36 + c0h + 4];
            }
#pragma unroll
            for (int tm = 0; tm < 4; tm++)
#pragma unroll
                for (int tn = 0; tn < 8; tn++)
                    mma_f16(acc[tm][tn], afrag[tm], bfrag[tn]);
        }
        __syncthreads();

        if (kt + 2 < NKTH) issue_stage(kt + 2);
    }

    // ---- Epilogue: bias + softplus, float2 stores into Q or R plane -------
    const bool is_q = (bn < H_DIM);
    float* plane = is_q ? g_Q : g_R;
    const int col_plane0 = bn & (H_DIM - 1);

#pragma unroll
    for (int tm = 0; tm < 4; tm++) {
#pragma unroll
        for (int tn = 0; tn < 8; tn++) {
#pragma unroll
            for (int half = 0; half < 2; half++) {
                int row = bm + wm + tm * 16 + (lane >> 2) + half * 8;
                int col = wn + tn * 8 + (lane & 3) * 2;
                int gcol = bn + col;
                float v0 = acc[tm][tn][half * 2 + 0] + __ldg(&bias[gcol]);
                float v1 = acc[tm][tn][half * 2 + 1] + __ldg(&bias[gcol + 1]);
                float2 sp;
                sp.x = softplus_f(v0);
                sp.y = softplus_f(v1);
                *(float2*)&plane[(size_t)row * H_DIM + col_plane0 + col] = sp;
            }
        }
    }
}

// ---------------------------------------------------------------------------
// Phase 2: Kalman scan, cp.async SMEM ring pipeline (unchanged from R6).
// ---------------------------------------------------------------------------
#define U 8
#define NCH (S_DIM / U)   // 512
#define DEPTH 8           // ring slots (power of 2)

__global__ void __launch_bounds__(32, 1)
scan_kernel(const float* __restrict__ lstm, float* __restrict__ out) {
    __shared__ float sbuf[DEPTH][3][U][32];

    const int lane = threadIdx.x;
    const int idx = blockIdx.x * 32 + lane;   // chain id 0..4095
    const int b = idx >> 9;
    const int h0 = (blockIdx.x * 32) & 511;   // block-uniform h base

    const size_t block_off = (size_t)b * S_DIM * H_DIM + h0;
    const float* zb = lstm + block_off;
    const float* qb = g_Q + block_off;
    const float* rb = g_R + block_off;
    float* op = out + (size_t)b * S_DIM * H_DIM + h0 + lane;

    const int cp_row = lane >> 3;        // 0..3
    const int cp_col = (lane & 7) * 4;   // float offset within row

    const float* srcs[3] = { zb, qb, rb };

    auto issue = [&](int c) {
        int slot = c & (DEPTH - 1);
#pragma unroll
        for (int a = 0; a < 3; a++) {
#pragma unroll
            for (int g = 0; g < 2; g++) {
                int row = g * 4 + cp_row;
                const float* src = srcs[a] + ((size_t)c * U + row) * H_DIM + cp_col;
                uint32_t dst = (uint32_t)__cvta_generic_to_shared(&sbuf[slot][a][row][cp_col]);
                asm volatile("cp.async.cg.shared.global [%0], [%1], 16;"
                             :: "r"(dst), "l"(src) : "memory");
            }
        }
        asm volatile("cp.async.commit_group;" ::: "memory");
    };

    float state = __ldg(zb + lane);   // lstm[b,0,h]
    float P = 0.1f;

#pragma unroll
    for (int d = 0; d < DEPTH - 1; d++) issue(d);

    for (int c = 0; c < NCH; c++) {
        asm volatile("cp.async.wait_group %0;" :: "n"(DEPTH - 2) : "memory");

        const int slot = c & (DEPTH - 1);
        float* oc = op + (size_t)c * U * H_DIM;
#pragma unroll
        for (int i = 0; i < U; i++) {
            float z = sbuf[slot][0][i][lane];
            float q = sbuf[slot][1][i][lane];
            float r = sbuf[slot][2][i][lane];
            float P_pred = P + q;
            float rr = r + 1e-6f;
            float denom = P_pred + rr;
            float inv;
            asm("rcp.approx.f32 %0, %1;" : "=f"(inv) : "f"(denom));
            float K = P_pred * inv;
            state = fmaf(K, z - state, state);
            P = P_pred * rr * inv;   // == (1-K)*P_pred
            oc[(size_t)i * H_DIM] = state;
        }

        if (c + DEPTH - 1 < NCH) issue(c + DEPTH - 1);
    }
}

extern "C" void kernel_launch(void* const* d_in, const int* in_sizes, int n_in,
                              void* d_out, int out_size) {
    const float* lstm = (const float*)d_in[0];
    const float* W    = (const float*)d_in[1];
    const float* bias = (const float*)d_in[2];
    float* out = (float*)d_out;

    __half* Ah; __half* Wh;
    cudaGetSymbolAddress((void**)&Ah, g_Ah);
    cudaGetSymbolAddress((void**)&Wh, g_Wh);

    // pre-pass conversions
    cvt_fp16_kernel<<<2048, 256>>>(lstm, Ah, (M_TOT * K_TOT) / 4);
    cvt_fp16_kernel<<<256, 256>>>(W, Wh, (N_TOT * K_TOT) / 4);

    cudaFuncSetAttribute(gemm_softplus_kernel,
                         cudaFuncAttributeMaxDynamicSharedMemorySize, DYN_BYTES);

    dim3 grid2(N_TOT / BN2, M_TOT / BM2);   // (4, 256)
    gemm_softplus_kernel<<<grid2, 256, DYN_BYTES>>>(Ah, Wh, bias);

    scan_kernel<<<128, 32>>>(lstm, out);
}

// round 10
// speedup vs baseline: 2.6528x; 1.4561x over previous
#include <cuda_runtime.h>
#include <cuda_fp16.h>
#include <cstdint>

#define B_DIM 8
#define S_DIM 4096
#define H_DIM 512
#define M_TOT (B_DIM * S_DIM)   // 32768
#define N_TOT (2 * H_DIM)       // 1024
#define K_TOT H_DIM             // 512

// Scratch planes in [b, s, h] layout (same as lstm/out).
__device__ float g_Q[(size_t)M_TOT * H_DIM];  // 64 MB
__device__ float g_R[(size_t)M_TOT * H_DIM];  // 64 MB
// fp16 copies of A and W for the 2x-rate fp16 tensor path.
__device__ __half g_Ah[(size_t)M_TOT * K_TOT];  // 32 MB
__device__ __half g_Wh[(size_t)N_TOT * K_TOT];  // 1 MB

// ===========================================================================
// Pre-pass: fp32 -> fp16 conversion (grid-stride, float4 -> half2 x2).
// ===========================================================================
__global__ void cvt_fp16_kernel(const float* __restrict__ src,
                                __half* __restrict__ dst, int n4) {
    int i = blockIdx.x * blockDim.x + threadIdx.x;
    int stride = gridDim.x * blockDim.x;
    for (; i < n4; i += stride) {
        float4 v = ((const float4*)src)[i];
        __half2 h0 = __floats2half2_rn(v.x, v.y);
        __half2 h1 = __floats2half2_rn(v.z, v.w);
        ((__half2*)dst)[2 * i]     = h0;
        ((__half2*)dst)[2 * i + 1] = h1;
    }
}

// ===========================================================================
// Phase 1: C = A*W^T + b, softplus -> Q/R planes.  (unchanged from R9)
// fp16 mma.sync m16n8k16; BM=128, BN=256, BK=64; 3-stage cp.async ring.
// ===========================================================================

#define BM2 128
#define BN2 256
#define BKH 64                    // k per ktile (halves) = 128B rows
#define NKTH (K_TOT / BKH)        // 8
#define ROWH 72                   // halves per row incl. 8-half skew (144B)
#define A_HALVES (BM2 * ROWH)     // 9216
#define B_HALVES (BN2 * ROWH)     // 18432
#define STAGE_HALVES (A_HALVES + B_HALVES)     // 27648
#define NSTAGE 3
#define DYN_BYTES (NSTAGE * STAGE_HALVES * 2)  // 165888

__device__ __forceinline__ float softplus_f(float x) {
    return fmaxf(x, 0.0f) + log1pf(__expf(-fabsf(x)));
}

__device__ __forceinline__ void mma_f16(float c[4], const uint32_t a[4], const uint32_t b[2]) {
    asm volatile(
        "mma.sync.aligned.m16n8k16.row.col.f32.f16.f16.f32 "
        "{%0,%1,%2,%3}, {%4,%5,%6,%7}, {%8,%9}, {%0,%1,%2,%3};"
        : "+f"(c[0]), "+f"(c[1]), "+f"(c[2]), "+f"(c[3])
        : "r"(a[0]), "r"(a[1]), "r"(a[2]), "r"(a[3]), "r"(b[0]), "r"(b[1]));
}

__global__ void __launch_bounds__(256, 1)
gemm_softplus_kernel(const __half* __restrict__ A,
                     const __half* __restrict__ W,
                     const float* __restrict__ bias) {
    extern __shared__ __half dynh[];

    const int tid  = threadIdx.x;
    const int warp = tid >> 5;
    const int lane = tid & 31;
    const int bm = blockIdx.y * BM2;
    const int bn = blockIdx.x * BN2;

    const int wm = (warp >> 2) * 64;
    const int wn = (warp & 3) * 64;

    float acc[4][8][4];
#pragma unroll
    for (int i = 0; i < 4; i++)
#pragma unroll
        for (int j = 0; j < 8; j++)
#pragma unroll
            for (int c = 0; c < 4; c++) acc[i][j][c] = 0.0f;

    auto issue_stage = [&](int kt) {
        const int s = kt % NSTAGE;
        __half* As = dynh + s * STAGE_HALVES;
        __half* Bs = As + A_HALVES;
        const int kcol = kt * BKH;
#pragma unroll
        for (int i = 0; i < 4; i++) {
            int j = tid + i * 256;
            int row = j >> 3, cb = j & 7;
            const __half* src = A + (size_t)(bm + row) * K_TOT + kcol + cb * 8;
            uint32_t dst = (uint32_t)__cvta_generic_to_shared(As + row * ROWH + cb * 8);
            asm volatile("cp.async.cg.shared.global [%0], [%1], 16;"
                         :: "r"(dst), "l"(src) : "memory");
        }
#pragma unroll
        for (int i = 0; i < 8; i++) {
            int j = tid + i * 256;
            int row = j >> 3, cb = j & 7;
            const __half* src = W + (size_t)(bn + row) * K_TOT + kcol + cb * 8;
            uint32_t dst = (uint32_t)__cvta_generic_to_shared(Bs + row * ROWH + cb * 8);
            asm volatile("cp.async.cg.shared.global [%0], [%1], 16;"
                         :: "r"(dst), "l"(src) : "memory");
        }
        asm volatile("cp.async.commit_group;" ::: "memory");
    };

    issue_stage(0);
    issue_stage(1);

    for (int kt = 0; kt < NKTH; kt++) {
        if (kt == NKTH - 1) asm volatile("cp.async.wait_group 0;" ::: "memory");
        else                asm volatile("cp.async.wait_group 1;" ::: "memory");
        __syncthreads();

        const int s = kt % NSTAGE;
        const uint32_t* As32 = (const uint32_t*)(dynh + s * STAGE_HALVES);
        const uint32_t* Bs32 = As32 + A_HALVES / 2;

#pragma unroll
        for (int ks = 0; ks < 4; ks++) {
            const int c0h = ks * 8 + (lane & 3);
            uint32_t afrag[4][4];
            uint32_t bfrag[8][2];
#pragma unroll
            for (int tm = 0; tm < 4; tm++) {
                int r0 = wm + tm * 16 + (lane >> 2);
                afrag[tm][0] = As32[r0 * 36 + c0h];
                afrag[tm][1] = As32[(r0 + 8) * 36 + c0h];
                afrag[tm][2] = As32[r0 * 36 + c0h + 4];
                afrag[tm][3] = As32[(r0 + 8) * 36 + c0h + 4];
            }
#pragma unroll
            for (int tn = 0; tn < 8; tn++) {
                int rb = wn + tn * 8 + (lane >> 2);
                bfrag[tn][0] = Bs32[rb * 36 + c0h];
                bfrag[tn][1] = Bs32[rb * 36 + c0h + 4];
            }
#pragma unroll
            for (int tm = 0; tm < 4; tm++)
#pragma unroll
                for (int tn = 0; tn < 8; tn++)
                    mma_f16(acc[tm][tn], afrag[tm], bfrag[tn]);
        }
        __syncthreads();

        if (kt + 2 < NKTH) issue_stage(kt + 2);
    }

    const bool is_q = (bn < H_DIM);
    float* plane = is_q ? g_Q : g_R;
    const int col_plane0 = bn & (H_DIM - 1);

#pragma unroll
    for (int tm = 0; tm < 4; tm++) {
#pragma unroll
        for (int tn = 0; tn < 8; tn++) {
#pragma unroll
            for (int half = 0; half < 2; half++) {
                int row = bm + wm + tm * 16 + (lane >> 2) + half * 8;
                int col = wn + tn * 8 + (lane & 3) * 2;
                int gcol = bn + col;
                float v0 = acc[tm][tn][half * 2 + 0] + __ldg(&bias[gcol]);
                float v1 = acc[tm][tn][half * 2 + 1] + __ldg(&bias[gcol + 1]);
                float2 sp;
                sp.x = softplus_f(v0);
                sp.y = softplus_f(v1);
                *(float2*)&plane[(size_t)row * H_DIM + col_plane0 + col] = sp;
            }
        }
    }
}

// ---------------------------------------------------------------------------
// Phase 2: SEGMENTED Kalman scan. Each chain split into 8 segments of 512
// steps; segments >0 warm up over the previous 128 steps (contraction
// (1-K)^128 < 1e-6 kills init error). 8x parallelism: 32768 threads, scan
// becomes memory-bound. cp.async ring pipeline per warp as before.
// ---------------------------------------------------------------------------
#define U 8
#define DEPTH 8             // ring slots (power of 2)
#define SEG 512             // output steps per segment
#define NSEG (S_DIM / SEG)  // 8
#define SEGCH (SEG / U)     // 64 chunks stored per segment
#define WARMCH 16           // 128 warm-up steps

__global__ void __launch_bounds__(32, 1)
scan_kernel(const float* __restrict__ lstm, float* __restrict__ out) {
    __shared__ float sbuf[DEPTH][3][U][32];

    const int lane = threadIdx.x;
    const int chainblk = blockIdx.x & 127;    // 128 chain-blocks of 32 chains
    const int seg = blockIdx.x >> 7;          // 0..7
    const int b = chainblk >> 4;              // 16 blocks per batch
    const int h0 = (chainblk * 32) & 511;

    const size_t block_off = (size_t)b * S_DIM * H_DIM + h0;
    const float* zb = lstm + block_off;
    const float* qb = g_Q + block_off;
    const float* rb = g_R + block_off;
    float* op = out + block_off + lane;

    const int cp_row = lane >> 3;
    const int cp_col = (lane & 7) * 4;

    const float* srcs[3] = { zb, qb, rb };

    // issue chunk c into ring slot `slot`
    auto issue = [&](int c, int slot) {
#pragma unroll
        for (int a = 0; a < 3; a++) {
#pragma unroll
            for (int g = 0; g < 2; g++) {
                int row = g * 4 + cp_row;
                const float* src = srcs[a] + ((size_t)c * U + row) * H_DIM + cp_col;
                uint32_t dst = (uint32_t)__cvta_generic_to_shared(&sbuf[slot][a][row][cp_col]);
                asm volatile("cp.async.cg.shared.global [%0], [%1], 16;"
                             :: "r"(dst), "l"(src) : "memory");
            }
        }
        asm volatile("cp.async.commit_group;" ::: "memory");
    };

    const int cstore = seg * SEGCH;
    const int c0 = (seg == 0) ? 0 : cstore - WARMCH;
    const int cend = cstore + SEGCH;

    float state, P;
    if (seg == 0) {
        state = __ldg(zb + lane);   // exact init
        P = 0.1f;
    } else {
        state = __ldg(zb + (size_t)c0 * U * H_DIM + lane);  // any init; warm-up converges
        P = 1.0f;
    }

#pragma unroll
    for (int d = 0; d < DEPTH - 1; d++) {
        int c = c0 + d;
        if (c > cend - 1) c = cend - 1;
        issue(c, (c0 + d) & (DEPTH - 1));
    }

    for (int c = c0; c < cend; c++) {
        asm volatile("cp.async.wait_group %0;" :: "n"(DEPTH - 2) : "memory");

        const int slot = c & (DEPTH - 1);
        const bool do_store = (c >= cstore);
        float* oc = op + (size_t)c * U * H_DIM;
#pragma unroll
        for (int i = 0; i < U; i++) {
            float z = sbuf[slot][0][i][lane];
            float q = sbuf[slot][1][i][lane];
            float r = sbuf[slot][2][i][lane];
            float P_pred = P + q;
            float rr = r + 1e-6f;
            float denom = P_pred + rr;
            float inv;
            asm("rcp.approx.f32 %0, %1;" : "=f"(inv) : "f"(denom));
            float K = P_pred * inv;
            state = fmaf(K, z - state, state);
            P = P_pred * rr * inv;   // == (1-K)*P_pred
            if (do_store) oc[(size_t)i * H_DIM] = state;
        }

        // always issue (clamped) so wait_group 6 provably covers slot c
        int cn = c + DEPTH - 1;
        if (cn > cend - 1) cn = cend - 1;
        issue(cn, (c + DEPTH - 1) & (DEPTH - 1));
    }
    asm volatile("cp.async.wait_group 0;" ::: "memory");   // drain before exit
}

extern "C" void kernel_launch(void* const* d_in, const int* in_sizes, int n_in,
                              void* d_out, int out_size) {
    const float* lstm = (const float*)d_in[0];
    const float* W    = (const float*)d_in[1];
    const float* bias = (const float*)d_in[2];
    float* out = (float*)d_out;

    __half* Ah; __half* Wh;
    cudaGetSymbolAddress((void**)&Ah, g_Ah);
    cudaGetSymbolAddress((void**)&Wh, g_Wh);

    cvt_fp16_kernel<<<2048, 256>>>(lstm, Ah, (M_TOT * K_TOT) / 4);
    cvt_fp16_kernel<<<256, 256>>>(W, Wh, (N_TOT * K_TOT) / 4);

    cudaFuncSetAttribute(gemm_softplus_kernel,
                         cudaFuncAttributeMaxDynamicSharedMemorySize, DYN_BYTES);

    dim3 grid2(N_TOT / BN2, M_TOT / BM2);   // (4, 256)
    gemm_softplus_kernel<<<grid2, 256, DYN_BYTES>>>(Ah, Wh, bias);

    scan_kernel<<<128 * NSEG, 32>>>(lstm, out);
}

// round 11
// speedup vs baseline: 2.8574x; 1.0771x over previous
#include <cuda_runtime.h>
#include <cuda_fp16.h>
#include <cstdint>

#define B_DIM 8
#define S_DIM 4096
#define H_DIM 512
#define M_TOT (B_DIM * S_DIM)   // 32768
#define N_TOT (2 * H_DIM)       // 1024
#define K_TOT H_DIM             // 512

// Q/R scratch planes in [b, s, h] layout, fp16 (halves traffic both phases).
__device__ __half g_Qh[(size_t)M_TOT * H_DIM];  // 32 MB
__device__ __half g_Rh[(size_t)M_TOT * H_DIM];  // 32 MB
// fp16 copies of A and W for the 2x-rate fp16 tensor path.
__device__ __half g_Ah[(size_t)M_TOT * K_TOT];  // 32 MB
__device__ __half g_Wh[(size_t)N_TOT * K_TOT];  // 1 MB

// ===========================================================================
// Pre-pass: fp32 -> fp16 conversion for A and W in ONE launch.
// ===========================================================================
__global__ void cvt_fp16_both(const float* __restrict__ a, __half* __restrict__ ah, int na4,
                              const float* __restrict__ w, __half* __restrict__ wh, int nw4) {
    int i = blockIdx.x * blockDim.x + threadIdx.x;
    int stride = gridDim.x * blockDim.x;
    int ntot = na4 + nw4;
    for (; i < ntot; i += stride) {
        const float4* s4;
        __half2* d2;
        int j;
        if (i < na4) { s4 = (const float4*)a; d2 = (__half2*)ah; j = i; }
        else         { s4 = (const float4*)w; d2 = (__half2*)wh; j = i - na4; }
        float4 v = s4[j];
        d2[2 * j]     = __floats2half2_rn(v.x, v.y);
        d2[2 * j + 1] = __floats2half2_rn(v.z, v.w);
    }
}

// ===========================================================================
// Phase 1: C = A*W^T + b, softplus -> fp16 Q/R planes.
// fp16 mma.sync m16n8k16; BM=128, BN=256, BK=64; 3-stage cp.async ring.
// ===========================================================================

#define BM2 128
#define BN2 256
#define BKH 64                    // k per ktile (halves) = 128B rows
#define NKTH (K_TOT / BKH)        // 8
#define ROWH 72                   // halves per row incl. 8-half skew (144B)
#define A_HALVES (BM2 * ROWH)     // 9216
#define B_HALVES (BN2 * ROWH)     // 18432
#define STAGE_HALVES (A_HALVES + B_HALVES)     // 27648
#define NSTAGE 3
#define DYN_BYTES (NSTAGE * STAGE_HALVES * 2)  // 165888

__device__ __forceinline__ float softplus_f(float x) {
    return fmaxf(x, 0.0f) + log1pf(__expf(-fabsf(x)));
}

__device__ __forceinline__ void mma_f16(float c[4], const uint32_t a[4], const uint32_t b[2]) {
    asm volatile(
        "mma.sync.aligned.m16n8k16.row.col.f32.f16.f16.f32 "
        "{%0,%1,%2,%3}, {%4,%5,%6,%7}, {%8,%9}, {%0,%1,%2,%3};"
        : "+f"(c[0]), "+f"(c[1]), "+f"(c[2]), "+f"(c[3])
        : "r"(a[0]), "r"(a[1]), "r"(a[2]), "r"(a[3]), "r"(b[0]), "r"(b[1]));
}

__global__ void __launch_bounds__(256, 1)
gemm_softplus_kernel(const __half* __restrict__ A,
                     const __half* __restrict__ W,
                     const float* __restrict__ bias) {
    extern __shared__ __half dynh[];

    const int tid  = threadIdx.x;
    const int warp = tid >> 5;
    const int lane = tid & 31;
    const int bm = blockIdx.y * BM2;
    const int bn = blockIdx.x * BN2;

    const int wm = (warp >> 2) * 64;
    const int wn = (warp & 3) * 64;

    float acc[4][8][4];
#pragma unroll
    for (int i = 0; i < 4; i++)
#pragma unroll
        for (int j = 0; j < 8; j++)
#pragma unroll
            for (int c = 0; c < 4; c++) acc[i][j][c] = 0.0f;

    auto issue_stage = [&](int kt) {
        const int s = kt % NSTAGE;
        __half* As = dynh + s * STAGE_HALVES;
        __half* Bs = As + A_HALVES;
        const int kcol = kt * BKH;
#pragma unroll
        for (int i = 0; i < 4; i++) {
            int j = tid + i * 256;
            int row = j >> 3, cb = j & 7;
            const __half* src = A + (size_t)(bm + row) * K_TOT + kcol + cb * 8;
            uint32_t dst = (uint32_t)__cvta_generic_to_shared(As + row * ROWH + cb * 8);
            asm volatile("cp.async.cg.shared.global [%0], [%1], 16;"
                         :: "r"(dst), "l"(src) : "memory");
        }
#pragma unroll
        for (int i = 0; i < 8; i++) {
            int j = tid + i * 256;
            int row = j >> 3, cb = j & 7;
            const __half* src = W + (size_t)(bn + row) * K_TOT + kcol + cb * 8;
            uint32_t dst = (uint32_t)__cvta_generic_to_shared(Bs + row * ROWH + cb * 8);
            asm volatile("cp.async.cg.shared.global [%0], [%1], 16;"
                         :: "r"(dst), "l"(src) : "memory");
        }
        asm volatile("cp.async.commit_group;" ::: "memory");
    };

    issue_stage(0);
    issue_stage(1);

    for (int kt = 0; kt < NKTH; kt++) {
        if (kt == NKTH - 1) asm volatile("cp.async.wait_group 0;" ::: "memory");
        else                asm volatile("cp.async.wait_group 1;" ::: "memory");
        __syncthreads();

        const int s = kt % NSTAGE;
        const uint32_t* As32 = (const uint32_t*)(dynh + s * STAGE_HALVES);
        const uint32_t* Bs32 = As32 + A_HALVES / 2;

#pragma unroll
        for (int ks = 0; ks < 4; ks++) {
            const int c0h = ks * 8 + (lane & 3);
            uint32_t afrag[4][4];
            uint32_t bfrag[8][2];
#pragma unroll
            for (int tm = 0; tm < 4; tm++) {
                int r0 = wm + tm * 16 + (lane >> 2);
                afrag[tm][0] = As32[r0 * 36 + c0h];
                afrag[tm][1] = As32[(r0 + 8) * 36 + c0h];
                afrag[tm][2] = As32[r0 * 36 + c0h + 4];
                afrag[tm][3] = As32[(r0 + 8) * 36 + c0h + 4];
            }
#pragma unroll
            for (int tn = 0; tn < 8; tn++) {
                int rb = wn + tn * 8 + (lane >> 2);
                bfrag[tn][0] = Bs32[rb * 36 + c0h];
                bfrag[tn][1] = Bs32[rb * 36 + c0h + 4];
            }
#pragma unroll
            for (int tm = 0; tm < 4; tm++)
#pragma unroll
                for (int tn = 0; tn < 8; tn++)
                    mma_f16(acc[tm][tn], afrag[tm], bfrag[tn]);
        }
        __syncthreads();

        if (kt + 2 < NKTH) issue_stage(kt + 2);
    }

    // ---- Epilogue: bias + softplus, half2 stores into fp16 Q or R plane ---
    const bool is_q = (bn < H_DIM);
    __half* plane = is_q ? g_Qh : g_Rh;
    const int col_plane0 = bn & (H_DIM - 1);

#pragma unroll
    for (int tm = 0; tm < 4; tm++) {
#pragma unroll
        for (int tn = 0; tn < 8; tn++) {
#pragma unroll
            for (int half = 0; half < 2; half++) {
                int row = bm + wm + tm * 16 + (lane >> 2) + half * 8;
                int col = wn + tn * 8 + (lane & 3) * 2;
                int gcol = bn + col;
                float v0 = acc[tm][tn][half * 2 + 0] + __ldg(&bias[gcol]);
                float v1 = acc[tm][tn][half * 2 + 1] + __ldg(&bias[gcol + 1]);
                __half2 hp = __floats2half2_rn(softplus_f(v0), softplus_f(v1));
                *(__half2*)&plane[(size_t)row * H_DIM + col_plane0 + col] = hp;
            }
        }
    }
}

// ---------------------------------------------------------------------------
// Phase 2: SEGMENTED Kalman scan (fp16 q/r). 8 segments x 512 steps, 128-step
// warm-up (contraction (1-K)^128 kills init error). cp.async ring; 4 copies
// per chunk (z: 2x16B/lane, q: 1, r: 1).
// ---------------------------------------------------------------------------
#define U 8
#define DEPTH 8             // ring slots (power of 2)
#define SEG 512             // output steps per segment
#define NSEG (S_DIM / SEG)  // 8
#define SEGCH (SEG / U)     // 64 chunks stored per segment
#define WARMCH 16           // 128 warm-up steps

__global__ void __launch_bounds__(32, 1)
scan_kernel(const float* __restrict__ lstm, float* __restrict__ out) {
    __shared__ float  sz[DEPTH][U][32];
    __shared__ __half sq[DEPTH][U][32];
    __shared__ __half sr[DEPTH][U][32];

    const int lane = threadIdx.x;
    const int chainblk = blockIdx.x & 127;    // 128 chain-blocks of 32 chains
    const int seg = blockIdx.x >> 7;          // 0..7
    const int b = chainblk >> 4;              // 16 blocks per batch
    const int h0 = (chainblk * 32) & 511;

    const size_t block_off = (size_t)b * S_DIM * H_DIM + h0;
    const float*  zb = lstm + block_off;
    const __half* qb = g_Qh + block_off;
    const __half* rb = g_Rh + block_off;
    float* op = out + block_off + lane;

    // z mapping: 16B = 4 floats; 8 lanes per row, 2 groups of 4 rows
    const int zrow = lane >> 3;
    const int zcol = (lane & 7) * 4;
    // q/r mapping: 16B = 8 halves; 4 lanes per row, 8 rows
    const int hrow = lane >> 2;
    const int hcol = (lane & 3) * 8;

    auto issue = [&](int c, int slot) {
#pragma unroll
        for (int g = 0; g < 2; g++) {
            int row = g * 4 + zrow;
            const float* src = zb + ((size_t)c * U + row) * H_DIM + zcol;
            uint32_t dst = (uint32_t)__cvta_generic_to_shared(&sz[slot][row][zcol]);
            asm volatile("cp.async.cg.shared.global [%0], [%1], 16;"
                         :: "r"(dst), "l"(src) : "memory");
        }
        {
            const __half* src = qb + ((size_t)c * U + hrow) * H_DIM + hcol;
            uint32_t dst = (uint32_t)__cvta_generic_to_shared(&sq[slot][hrow][hcol]);
            asm volatile("cp.async.cg.shared.global [%0], [%1], 16;"
                         :: "r"(dst), "l"(src) : "memory");
        }
        {
            const __half* src = rb + ((size_t)c * U + hrow) * H_DIM + hcol;
            uint32_t dst = (uint32_t)__cvta_generic_to_shared(&sr[slot][hrow][hcol]);
            asm volatile("cp.async.cg.shared.global [%0], [%1], 16;"
                         :: "r"(dst), "l"(src) : "memory");
        }
        asm volatile("cp.async.commit_group;" ::: "memory");
    };

    const int cstore = seg * SEGCH;
    const int c0 = (seg == 0) ? 0 : cstore - WARMCH;
    const int cend = cstore + SEGCH;

    float state, P;
    if (seg == 0) {
        state = __ldg(zb + lane);   // exact init
        P = 0.1f;
    } else {
        state = __ldg(zb + (size_t)c0 * U * H_DIM + lane);  // warm-up converges
        P = 1.0f;
    }

#pragma unroll
    for (int d = 0; d < DEPTH - 1; d++) {
        int c = c0 + d;
        if (c > cend - 1) c = cend - 1;
        issue(c, (c0 + d) & (DEPTH - 1));
    }

    for (int c = c0; c < cend; c++) {
        asm volatile("cp.async.wait_group %0;" :: "n"(DEPTH - 2) : "memory");

        const int slot = c & (DEPTH - 1);
        const bool do_store = (c >= cstore);
        float* oc = op + (size_t)c * U * H_DIM;
#pragma unroll
        for (int i = 0; i < U; i++) {
            float z = sz[slot][i][lane];
            float q = __half2float(sq[slot][i][lane]);
            float r = __half2float(sr[slot][i][lane]);
            float P_pred = P + q;
            float rr = r + 1e-6f;
            float denom = P_pred + rr;
            float inv;
            asm("rcp.approx.f32 %0, %1;" : "=f"(inv) : "f"(denom));
            float K = P_pred * inv;
            state = fmaf(K, z - state, state);
            P = P_pred * rr * inv;   // == (1-K)*P_pred
            if (do_store) oc[(size_t)i * H_DIM] = state;
        }

        int cn = c + DEPTH - 1;
        if (cn > cend - 1) cn = cend - 1;
        issue(cn, (c + DEPTH - 1) & (DEPTH - 1));
    }
    asm volatile("cp.async.wait_group 0;" ::: "memory");   // drain before exit
}

extern "C" void kernel_launch(void* const* d_in, const int* in_sizes, int n_in,
                              void* d_out, int out_size) {
    const float* lstm = (const float*)d_in[0];
    const float* W    = (const float*)d_in[1];
    const float* bias = (const float*)d_in[2];
    float* out = (float*)d_out;

    __half* Ah; __half* Wh;
    cudaGetSymbolAddress((void**)&Ah, g_Ah);
    cudaGetSymbolAddress((void**)&Wh, g_Wh);

    cvt_fp16_both<<<2048, 256>>>(lstm, Ah, (M_TOT * K_TOT) / 4,
                                 W, Wh, (N_TOT * K_TOT) / 4);

    cudaFuncSetAttribute(gemm_softplus_kernel,
                         cudaFuncAttributeMaxDynamicSharedMemorySize, DYN_BYTES);

    dim3 grid2(N_TOT / BN2, M_TOT / BM2);   // (4, 256)
    gemm_softplus_kernel<<<grid2, 256, DYN_BYTES>>>(Ah, Wh, bias);

    scan_kernel<<<128 * NSEG, 32>>>(lstm, out);
}